// round 6
// baseline (speedup 1.0000x reference)
#include <cuda_runtime.h>
#include <math.h>
#include <float.h>

// ---------------- problem constants ----------------
// x: (B=16, C=1024, H=64, W=64) fp32. out: (16,1024,1,1) fp32.
// 14 distinct regions (full region weighted x2):
//  r0:  (0,0,64)
//  r1..r4:  wl=42 at (i,j) in {0,22}x{0,22}  (i-major)
//  r5..r13: wl=32 at (i,j) in {0,16,32}^2    (i-major)
#define B 16
#define C 1024
#define HW 64
#define NPIX 4096          // 64*64
#define NGRP 64            // channel groups (16 channels each)
#define NREG 14

// col-segment ids stored per row: 0=[0,64) 1=[0,42) 2=[22,64) 3=[0,32) 4=[16,48) 5=[32,64)
__constant__ int c_cs[NREG] = {0, 1,2,1,2, 3,4,5, 3,4,5, 3,4,5};
__constant__ int c_rs[NREG] = {0, 0,0,22,22, 0,0,0, 16,16,16, 32,32,32};
__constant__ int c_rl[NREG] = {64, 42,42,42,42, 32,32,32,32,32,32,32,32,32};
__constant__ float c_area[NREG] = {4096.f, 1764.f,1764.f,1764.f,1764.f,
                                   1024.f,1024.f,1024.f,1024.f,1024.f,1024.f,1024.f,1024.f,1024.f};

// ---------------- device scratch (no allocations allowed) ----------------
__device__ float g_spart[NGRP * B * NPIX];   // 16.8 MB partial channel sums
__device__ float g_s[B * NPIX];              // channel sums
__device__ float g_btot[64];                 // per-block totals of s
__device__ float g_vt[NREG * B * C];         // region maxes
__device__ int   g_cnt[NREG];                // tt counts per region

// elementary col segments: E0[0,16) E1[16,22) E2[22,32) E3[32,42) E4[42,48) E5[48,64)
#define UPDSEG(W, V) do { \
    if ((W) < 16)      e0 = fmaxf(e0, (V)); \
    else if ((W) < 22) e1 = fmaxf(e1, (V)); \
    else if ((W) < 32) e2 = fmaxf(e2, (V)); \
    else if ((W) < 42) e3 = fmaxf(e3, (V)); \
    else if ((W) < 48) e4 = fmaxf(e4, (V)); \
    else               e5 = fmaxf(e5, (V)); } while (0)

// ================= kernel A: single pass over x =================
// grid (64 groups, 16 batches), block = 64 threads (thread = row h).
// Per block: 16 channels. Computes per-channel row col-segment maxes into smem,
// then reduces rows -> 14 region maxes; accumulates channel partial sums per pixel.
__global__ __launch_bounds__(64) void kA(const float* __restrict__ x) {
    const int g = blockIdx.x;     // channel group 0..63
    const int b = blockIdx.y;     // batch
    const int h = threadIdx.x;    // row 0..63

    __shared__ float need[16 * 64 * 6];   // [c_local][row][colseg] 24 KB

    float4 sums[16];
#pragma unroll
    for (int i = 0; i < 16; i++) sums[i] = make_float4(0.f, 0.f, 0.f, 0.f);

#pragma unroll 1
    for (int cl = 0; cl < 16; cl++) {
        const int c = g * 16 + cl;
        const float4* __restrict__ xr = reinterpret_cast<const float4*>(
            x + ((((size_t)b * C + c) * HW + h) * HW));
        float e0 = -INFINITY, e1 = -INFINITY, e2 = -INFINITY,
              e3 = -INFINITY, e4 = -INFINITY, e5 = -INFINITY;
#pragma unroll
        for (int i = 0; i < 16; i++) {
            float4 v = xr[i];
            sums[i].x += v.x; sums[i].y += v.y; sums[i].z += v.z; sums[i].w += v.w;
            UPDSEG(4*i + 0, v.x);
            UPDSEG(4*i + 1, v.y);
            UPDSEG(4*i + 2, v.z);
            UPDSEG(4*i + 3, v.w);
        }
        // combine elementary -> needed col segments
        float c32_0 = fmaxf(fmaxf(e0, e1), e2);            // [0,32)
        float c32_2 = fmaxf(fmaxf(e3, e4), e5);            // [32,64)
        float c32_1 = fmaxf(fmaxf(e1, e2), fmaxf(e3, e4)); // [16,48)
        float c42_0 = fmaxf(c32_0, e3);                    // [0,42)
        float c42_1 = fmaxf(e2, c32_2);                    // [22,64)
        float cfull = fmaxf(c42_0, fmaxf(e4, e5));         // [0,64)
        float* nd = &need[(cl * 64 + h) * 6];
        nd[0] = cfull; nd[1] = c42_0; nd[2] = c42_1;
        nd[3] = c32_0; nd[4] = c32_1; nd[5] = c32_2;
    }
    __syncthreads();

    // phase 2: 224 jobs = 16 channels x 14 regions; reduce rows within region
    for (int j = threadIdx.x; j < 16 * NREG; j += 64) {
        const int cl = j / NREG;
        const int r  = j % NREG;
        const int cs = c_cs[r];
        const int h0 = c_rs[r];
        const int len = c_rl[r];
        const float* base = &need[cl * 64 * 6 + cs];
        float m = -INFINITY;
#pragma unroll 8
        for (int hh = h0; hh < h0 + len; hh++) m = fmaxf(m, base[hh * 6]);
        g_vt[(r * B + b) * C + g * 16 + cl] = m;
    }

    // write partial channel sums (deterministic scratch, reduced in kB1)
    float4* sp = reinterpret_cast<float4*>(&g_spart[((size_t)(g * B + b)) * NPIX + h * HW]);
#pragma unroll
    for (int i = 0; i < 16; i++) sp[i] = sums[i];
}

// ================= kernel B1: reduce partials -> s, block totals =================
__global__ __launch_bounds__(1024) void kB1() {
    const int tid = threadIdx.x;
    const int gp = blockIdx.x * 1024 + tid;   // global pixel over (b, p)
    float sv = 0.f;
#pragma unroll 8
    for (int g2 = 0; g2 < NGRP; g2++) sv += g_spart[(size_t)g2 * (B * NPIX) + gp];
    g_s[gp] = sv;

    __shared__ float red[1024];
    red[tid] = sv;
    __syncthreads();
    for (int off = 512; off > 0; off >>= 1) {
        if (tid < off) red[tid] += red[tid + off];
        __syncthreads();
    }
    if (tid == 0) g_btot[blockIdx.x] = red[0];
    if (blockIdx.x == 0 && tid < NREG) g_cnt[tid] = 0;  // zero counters for kB2
}

// ================= kernel B2: mean + per-region tt counts =================
__global__ __launch_bounds__(1024) void kB2() {
    __shared__ float s_mean;
    const int tid = threadIdx.x;
    if (tid == 0) {
        float t = 0.f;
        for (int i = 0; i < 64; i++) t += g_btot[i];
        s_mean = t / (float)(B * NPIX);
    }
    __syncthreads();

    const int gp = blockIdx.x * 1024 + tid;
    const float sv = g_s[gp];
    const bool tt = (sv - s_mean) > 0.f;
    const int p = gp & (NPIX - 1);
    const int h = p >> 6;
    const int w = p & 63;

    const bool h42a = h < 42, h42b = h >= 22, w42a = w < 42, w42b = w >= 22;
    const bool h32a = h < 32, h32b = (h >= 16 && h < 48), h32c = h >= 32;
    const bool w32a = w < 32, w32b = (w >= 16 && w < 48), w32c = w >= 32;

    bool mem[NREG];
    mem[0]  = true;
    mem[1]  = h42a && w42a;  mem[2]  = h42a && w42b;
    mem[3]  = h42b && w42a;  mem[4]  = h42b && w42b;
    mem[5]  = h32a && w32a;  mem[6]  = h32a && w32b;  mem[7]  = h32a && w32c;
    mem[8]  = h32b && w32a;  mem[9]  = h32b && w32b;  mem[10] = h32b && w32c;
    mem[11] = h32c && w32a;  mem[12] = h32c && w32b;  mem[13] = h32c && w32c;

    unsigned bal[NREG];
#pragma unroll
    for (int r = 0; r < NREG; r++)
        bal[r] = __ballot_sync(0xffffffffu, tt && mem[r]);
    const int lane = tid & 31;
    if (lane < NREG) atomicAdd(&g_cnt[lane], __popc(bal[lane]));  // int atomics: deterministic
}

// ================= kernel C: norms + final combine =================
__global__ __launch_bounds__(1024) void kC(float* __restrict__ out) {
    const int b = blockIdx.x;
    const int c = threadIdx.x;
    const int warp = c >> 5;
    const int lane = c & 31;

    float val[NREG], ss[NREG];
#pragma unroll
    for (int r = 0; r < NREG; r++) {
        val[r] = g_vt[(r * B + b) * C + c];
        ss[r]  = val[r] * val[r];
    }
#pragma unroll
    for (int r = 0; r < NREG; r++)
        for (int o = 16; o > 0; o >>= 1)
            ss[r] += __shfl_xor_sync(0xffffffffu, ss[r], o);

    __shared__ float wsum[NREG][32];
    if (lane == 0) {
#pragma unroll
        for (int r = 0; r < NREG; r++) wsum[r][warp] = ss[r];
    }
    __syncthreads();

    __shared__ float scale_sh[NREG];
    if (warp < NREG) {
        float v = wsum[warp][lane];
        for (int o = 16; o > 0; o >>= 1)
            v += __shfl_xor_sync(0xffffffffu, v, o);
        if (lane == 0) {
            const float nrm = sqrtf(v);
            float wgt = (float)g_cnt[warp] / c_area[warp];
            if (wgt <= (1.0f / 3.0f)) wgt = 0.f;
            if (warp == 0) wgt *= 2.0f;           // full region appears twice
            scale_sh[warp] = wgt / (nrm + 1e-6f);
        }
    }
    __syncthreads();

    float o = 0.f;
#pragma unroll
    for (int r = 0; r < NREG; r++) o += val[r] * scale_sh[r];
    out[b * C + c] = o;
}

// ================= launch =================
extern "C" void kernel_launch(void* const* d_in, const int* in_sizes, int n_in,
                              void* d_out, int out_size) {
    const float* x = (const float*)d_in[0];
    float* out = (float*)d_out;
    kA<<<dim3(NGRP, B), 64>>>(x);
    kB1<<<64, 1024>>>();
    kB2<<<64, 1024>>>();
    kC<<<B, 1024>>>(out);
}

// round 7
// speedup vs baseline: 1.0013x; 1.0013x over previous
#include <cuda_runtime.h>
#include <math.h>
#include <float.h>

// ---------------- problem constants ----------------
// x: (B=16, C=1024, H=64, W=64) fp32. out: (16,1024,1,1) fp32.
// 14 distinct regions (full region weighted x2):
//  r0:  (0,0,64)
//  r1..r4:  wl=42 at (i,j) in {0,22}x{0,22}  (i-major)
//  r5..r13: wl=32 at (i,j) in {0,16,32}^2    (i-major)
#define B 16
#define C 1024
#define HW 64
#define NPIX 4096          // 64*64
#define NGRP 64            // channel groups (16 channels each)
#define NREG 14

// col-segment ids stored per row: 0=[0,64) 1=[0,42) 2=[22,64) 3=[0,32) 4=[16,48) 5=[32,64)
__constant__ int c_cs[NREG] = {0, 1,2,1,2, 3,4,5, 3,4,5, 3,4,5};
__constant__ int c_rs[NREG] = {0, 0,0,22,22, 0,0,0, 16,16,16, 32,32,32};
__constant__ int c_rl[NREG] = {64, 42,42,42,42, 32,32,32,32,32,32,32,32,32};
__constant__ float c_area[NREG] = {4096.f, 1764.f,1764.f,1764.f,1764.f,
                                   1024.f,1024.f,1024.f,1024.f,1024.f,1024.f,1024.f,1024.f,1024.f};

// ---------------- device scratch (no allocations allowed) ----------------
__device__ float g_spart[NGRP * B * NPIX];   // 16.8 MB partial channel sums
__device__ float g_s[B * NPIX];              // channel sums
__device__ float g_btot[64];                 // per-block totals of s
__device__ float g_vt[NREG * B * C];         // region maxes
__device__ int   g_cnt[NREG];                // tt counts per region

// elementary col segments: E0[0,16) E1[16,22) E2[22,32) E3[32,42) E4[42,48) E5[48,64)
#define UPDSEG(W, V) do { \
    if ((W) < 16)      e0 = fmaxf(e0, (V)); \
    else if ((W) < 22) e1 = fmaxf(e1, (V)); \
    else if ((W) < 32) e2 = fmaxf(e2, (V)); \
    else if ((W) < 42) e3 = fmaxf(e3, (V)); \
    else if ((W) < 48) e4 = fmaxf(e4, (V)); \
    else               e5 = fmaxf(e5, (V)); } while (0)

// ================= kernel A: single pass over x =================
// grid (64 groups, 16 batches), block = 64 threads (thread = row h).
// Per block: 16 channels. Computes per-channel row col-segment maxes into smem,
// then reduces rows -> 14 region maxes; accumulates channel partial sums per pixel.
__global__ __launch_bounds__(64) void kA(const float* __restrict__ x) {
    const int g = blockIdx.x;     // channel group 0..63
    const int b = blockIdx.y;     // batch
    const int h = threadIdx.x;    // row 0..63

    __shared__ float need[16 * 64 * 6];   // [c_local][row][colseg] 24 KB

    float4 sums[16];
#pragma unroll
    for (int i = 0; i < 16; i++) sums[i] = make_float4(0.f, 0.f, 0.f, 0.f);

#pragma unroll 1
    for (int cl = 0; cl < 16; cl++) {
        const int c = g * 16 + cl;
        const float4* __restrict__ xr = reinterpret_cast<const float4*>(
            x + ((((size_t)b * C + c) * HW + h) * HW));
        float e0 = -INFINITY, e1 = -INFINITY, e2 = -INFINITY,
              e3 = -INFINITY, e4 = -INFINITY, e5 = -INFINITY;
#pragma unroll
        for (int i = 0; i < 16; i++) {
            float4 v = xr[i];
            sums[i].x += v.x; sums[i].y += v.y; sums[i].z += v.z; sums[i].w += v.w;
            UPDSEG(4*i + 0, v.x);
            UPDSEG(4*i + 1, v.y);
            UPDSEG(4*i + 2, v.z);
            UPDSEG(4*i + 3, v.w);
        }
        // combine elementary -> needed col segments
        float c32_0 = fmaxf(fmaxf(e0, e1), e2);            // [0,32)
        float c32_2 = fmaxf(fmaxf(e3, e4), e5);            // [32,64)
        float c32_1 = fmaxf(fmaxf(e1, e2), fmaxf(e3, e4)); // [16,48)
        float c42_0 = fmaxf(c32_0, e3);                    // [0,42)
        float c42_1 = fmaxf(e2, c32_2);                    // [22,64)
        float cfull = fmaxf(c42_0, fmaxf(e4, e5));         // [0,64)
        float* nd = &need[(cl * 64 + h) * 6];
        nd[0] = cfull; nd[1] = c42_0; nd[2] = c42_1;
        nd[3] = c32_0; nd[4] = c32_1; nd[5] = c32_2;
    }
    __syncthreads();

    // phase 2: 224 jobs = 16 channels x 14 regions; reduce rows within region
    for (int j = threadIdx.x; j < 16 * NREG; j += 64) {
        const int cl = j / NREG;
        const int r  = j % NREG;
        const int cs = c_cs[r];
        const int h0 = c_rs[r];
        const int len = c_rl[r];
        const float* base = &need[cl * 64 * 6 + cs];
        float m = -INFINITY;
#pragma unroll 8
        for (int hh = h0; hh < h0 + len; hh++) m = fmaxf(m, base[hh * 6]);
        g_vt[(r * B + b) * C + g * 16 + cl] = m;
    }

    // write partial channel sums (deterministic scratch, reduced in kB1)
    float4* sp = reinterpret_cast<float4*>(&g_spart[((size_t)(g * B + b)) * NPIX + h * HW]);
#pragma unroll
    for (int i = 0; i < 16; i++) sp[i] = sums[i];
}

// ================= kernel B1: reduce partials -> s, block totals =================
__global__ __launch_bounds__(1024) void kB1() {
    const int tid = threadIdx.x;
    const int gp = blockIdx.x * 1024 + tid;   // global pixel over (b, p)
    float sv = 0.f;
#pragma unroll 8
    for (int g2 = 0; g2 < NGRP; g2++) sv += g_spart[(size_t)g2 * (B * NPIX) + gp];
    g_s[gp] = sv;

    __shared__ float red[1024];
    red[tid] = sv;
    __syncthreads();
    for (int off = 512; off > 0; off >>= 1) {
        if (tid < off) red[tid] += red[tid + off];
        __syncthreads();
    }
    if (tid == 0) g_btot[blockIdx.x] = red[0];
    if (blockIdx.x == 0 && tid < NREG) g_cnt[tid] = 0;  // zero counters for kB2
}

// ================= kernel B2: mean + per-region tt counts =================
__global__ __launch_bounds__(1024) void kB2() {
    __shared__ float s_mean;
    const int tid = threadIdx.x;
    if (tid == 0) {
        float t = 0.f;
        for (int i = 0; i < 64; i++) t += g_btot[i];
        s_mean = t / (float)(B * NPIX);
    }
    __syncthreads();

    const int gp = blockIdx.x * 1024 + tid;
    const float sv = g_s[gp];
    const bool tt = (sv - s_mean) > 0.f;
    const int p = gp & (NPIX - 1);
    const int h = p >> 6;
    const int w = p & 63;

    const bool h42a = h < 42, h42b = h >= 22, w42a = w < 42, w42b = w >= 22;
    const bool h32a = h < 32, h32b = (h >= 16 && h < 48), h32c = h >= 32;
    const bool w32a = w < 32, w32b = (w >= 16 && w < 48), w32c = w >= 32;

    bool mem[NREG];
    mem[0]  = true;
    mem[1]  = h42a && w42a;  mem[2]  = h42a && w42b;
    mem[3]  = h42b && w42a;  mem[4]  = h42b && w42b;
    mem[5]  = h32a && w32a;  mem[6]  = h32a && w32b;  mem[7]  = h32a && w32c;
    mem[8]  = h32b && w32a;  mem[9]  = h32b && w32b;  mem[10] = h32b && w32c;
    mem[11] = h32c && w32a;  mem[12] = h32c && w32b;  mem[13] = h32c && w32c;

    unsigned bal[NREG];
#pragma unroll
    for (int r = 0; r < NREG; r++)
        bal[r] = __ballot_sync(0xffffffffu, tt && mem[r]);
    const int lane = tid & 31;
    if (lane < NREG) atomicAdd(&g_cnt[lane], __popc(bal[lane]));  // int atomics: deterministic
}

// ================= kernel C: norms + final combine =================
__global__ __launch_bounds__(1024) void kC(float* __restrict__ out) {
    const int b = blockIdx.x;
    const int c = threadIdx.x;
    const int warp = c >> 5;
    const int lane = c & 31;

    float val[NREG], ss[NREG];
#pragma unroll
    for (int r = 0; r < NREG; r++) {
        val[r] = g_vt[(r * B + b) * C + c];
        ss[r]  = val[r] * val[r];
    }
#pragma unroll
    for (int r = 0; r < NREG; r++)
        for (int o = 16; o > 0; o >>= 1)
            ss[r] += __shfl_xor_sync(0xffffffffu, ss[r], o);

    __shared__ float wsum[NREG][32];
    if (lane == 0) {
#pragma unroll
        for (int r = 0; r < NREG; r++) wsum[r][warp] = ss[r];
    }
    __syncthreads();

    __shared__ float scale_sh[NREG];
    if (warp < NREG) {
        float v = wsum[warp][lane];
        for (int o = 16; o > 0; o >>= 1)
            v += __shfl_xor_sync(0xffffffffu, v, o);
        if (lane == 0) {
            const float nrm = sqrtf(v);
            float wgt = (float)g_cnt[warp] / c_area[warp];
            if (wgt <= (1.0f / 3.0f)) wgt = 0.f;
            if (warp == 0) wgt *= 2.0f;           // full region appears twice
            scale_sh[warp] = wgt / (nrm + 1e-6f);
        }
    }
    __syncthreads();

    float o = 0.f;
#pragma unroll
    for (int r = 0; r < NREG; r++) o += val[r] * scale_sh[r];
    out[b * C + c] = o;
}

// ================= launch =================
extern "C" void kernel_launch(void* const* d_in, const int* in_sizes, int n_in,
                              void* d_out, int out_size) {
    const float* x = (const float*)d_in[0];
    float* out = (float*)d_out;
    kA<<<dim3(NGRP, B), 64>>>(x);
    kB1<<<64, 1024>>>();
    kB2<<<64, 1024>>>();
    kC<<<B, 1024>>>(out);
}

// round 8
// speedup vs baseline: 1.0024x; 1.0011x over previous
#include <cuda_runtime.h>
#include <math.h>
#include <float.h>

// ---------------- problem constants ----------------
// x: (B=16, C=1024, H=64, W=64) fp32. out: (16,1024,1,1) fp32.
// 14 distinct regions (full region weighted x2):
//  r0:  (0,0,64)
//  r1..r4:  wl=42 at (i,j) in {0,22}x{0,22}  (i-major)
//  r5..r13: wl=32 at (i,j) in {0,16,32}^2    (i-major)
#define B 16
#define C 1024
#define HW 64
#define NPIX 4096          // 64*64
#define NGRP 64            // channel groups (16 channels each)
#define NREG 14

// col-segment ids stored per row: 0=[0,64) 1=[0,42) 2=[22,64) 3=[0,32) 4=[16,48) 5=[32,64)
__constant__ int c_cs[NREG] = {0, 1,2,1,2, 3,4,5, 3,4,5, 3,4,5};
__constant__ int c_rs[NREG] = {0, 0,0,22,22, 0,0,0, 16,16,16, 32,32,32};
__constant__ int c_rl[NREG] = {64, 42,42,42,42, 32,32,32,32,32,32,32,32,32};
__constant__ float c_area[NREG] = {4096.f, 1764.f,1764.f,1764.f,1764.f,
                                   1024.f,1024.f,1024.f,1024.f,1024.f,1024.f,1024.f,1024.f,1024.f};

// ---------------- device scratch (no allocations allowed) ----------------
__device__ float g_spart[NGRP * B * NPIX];   // 16.8 MB partial channel sums
__device__ float g_s[B * NPIX];              // channel sums
__device__ float g_btot[64];                 // per-block totals of s
__device__ float g_vt[NREG * B * C];         // region maxes
__device__ int   g_cnt[NREG];                // tt counts per region

// elementary col segments: E0[0,16) E1[16,22) E2[22,32) E3[32,42) E4[42,48) E5[48,64)
#define UPDSEG(W, V) do { \
    if ((W) < 16)      e0 = fmaxf(e0, (V)); \
    else if ((W) < 22) e1 = fmaxf(e1, (V)); \
    else if ((W) < 32) e2 = fmaxf(e2, (V)); \
    else if ((W) < 42) e3 = fmaxf(e3, (V)); \
    else if ((W) < 48) e4 = fmaxf(e4, (V)); \
    else               e5 = fmaxf(e5, (V)); } while (0)

// ================= kernel A: single pass over x =================
// grid (64 groups, 16 batches), block = 64 threads (thread = row h).
// Per block: 16 channels. Computes per-channel row col-segment maxes into smem,
// then reduces rows -> 14 region maxes; accumulates channel partial sums per pixel.
__global__ __launch_bounds__(64) void kA(const float* __restrict__ x) {
    const int g = blockIdx.x;     // channel group 0..63
    const int b = blockIdx.y;     // batch
    const int h = threadIdx.x;    // row 0..63

    __shared__ float need[16 * 64 * 6];   // [c_local][row][colseg] 24 KB

    float4 sums[16];
#pragma unroll
    for (int i = 0; i < 16; i++) sums[i] = make_float4(0.f, 0.f, 0.f, 0.f);

#pragma unroll 1
    for (int cl = 0; cl < 16; cl++) {
        const int c = g * 16 + cl;
        const float4* __restrict__ xr = reinterpret_cast<const float4*>(
            x + ((((size_t)b * C + c) * HW + h) * HW));
        float e0 = -INFINITY, e1 = -INFINITY, e2 = -INFINITY,
              e3 = -INFINITY, e4 = -INFINITY, e5 = -INFINITY;
#pragma unroll
        for (int i = 0; i < 16; i++) {
            float4 v = xr[i];
            sums[i].x += v.x; sums[i].y += v.y; sums[i].z += v.z; sums[i].w += v.w;
            UPDSEG(4*i + 0, v.x);
            UPDSEG(4*i + 1, v.y);
            UPDSEG(4*i + 2, v.z);
            UPDSEG(4*i + 3, v.w);
        }
        // combine elementary -> needed col segments
        float c32_0 = fmaxf(fmaxf(e0, e1), e2);            // [0,32)
        float c32_2 = fmaxf(fmaxf(e3, e4), e5);            // [32,64)
        float c32_1 = fmaxf(fmaxf(e1, e2), fmaxf(e3, e4)); // [16,48)
        float c42_0 = fmaxf(c32_0, e3);                    // [0,42)
        float c42_1 = fmaxf(e2, c32_2);                    // [22,64)
        float cfull = fmaxf(c42_0, fmaxf(e4, e5));         // [0,64)
        float* nd = &need[(cl * 64 + h) * 6];
        nd[0] = cfull; nd[1] = c42_0; nd[2] = c42_1;
        nd[3] = c32_0; nd[4] = c32_1; nd[5] = c32_2;
    }
    __syncthreads();

    // phase 2: 224 jobs = 16 channels x 14 regions; reduce rows within region
    for (int j = threadIdx.x; j < 16 * NREG; j += 64) {
        const int cl = j / NREG;
        const int r  = j % NREG;
        const int cs = c_cs[r];
        const int h0 = c_rs[r];
        const int len = c_rl[r];
        const float* base = &need[cl * 64 * 6 + cs];
        float m = -INFINITY;
#pragma unroll 8
        for (int hh = h0; hh < h0 + len; hh++) m = fmaxf(m, base[hh * 6]);
        g_vt[(r * B + b) * C + g * 16 + cl] = m;
    }

    // write partial channel sums (deterministic scratch, reduced in kB1)
    float4* sp = reinterpret_cast<float4*>(&g_spart[((size_t)(g * B + b)) * NPIX + h * HW]);
#pragma unroll
    for (int i = 0; i < 16; i++) sp[i] = sums[i];
}

// ================= kernel B1: reduce partials -> s, block totals =================
__global__ __launch_bounds__(1024) void kB1() {
    const int tid = threadIdx.x;
    const int gp = blockIdx.x * 1024 + tid;   // global pixel over (b, p)
    float sv = 0.f;
#pragma unroll 8
    for (int g2 = 0; g2 < NGRP; g2++) sv += g_spart[(size_t)g2 * (B * NPIX) + gp];
    g_s[gp] = sv;

    __shared__ float red[1024];
    red[tid] = sv;
    __syncthreads();
    for (int off = 512; off > 0; off >>= 1) {
        if (tid < off) red[tid] += red[tid + off];
        __syncthreads();
    }
    if (tid == 0) g_btot[blockIdx.x] = red[0];
    if (blockIdx.x == 0 && tid < NREG) g_cnt[tid] = 0;  // zero counters for kB2
}

// ================= kernel B2: mean + per-region tt counts =================
__global__ __launch_bounds__(1024) void kB2() {
    __shared__ float s_mean;
    const int tid = threadIdx.x;
    if (tid == 0) {
        float t = 0.f;
        for (int i = 0; i < 64; i++) t += g_btot[i];
        s_mean = t / (float)(B * NPIX);
    }
    __syncthreads();

    const int gp = blockIdx.x * 1024 + tid;
    const float sv = g_s[gp];
    const bool tt = (sv - s_mean) > 0.f;
    const int p = gp & (NPIX - 1);
    const int h = p >> 6;
    const int w = p & 63;

    const bool h42a = h < 42, h42b = h >= 22, w42a = w < 42, w42b = w >= 22;
    const bool h32a = h < 32, h32b = (h >= 16 && h < 48), h32c = h >= 32;
    const bool w32a = w < 32, w32b = (w >= 16 && w < 48), w32c = w >= 32;

    bool mem[NREG];
    mem[0]  = true;
    mem[1]  = h42a && w42a;  mem[2]  = h42a && w42b;
    mem[3]  = h42b && w42a;  mem[4]  = h42b && w42b;
    mem[5]  = h32a && w32a;  mem[6]  = h32a && w32b;  mem[7]  = h32a && w32c;
    mem[8]  = h32b && w32a;  mem[9]  = h32b && w32b;  mem[10] = h32b && w32c;
    mem[11] = h32c && w32a;  mem[12] = h32c && w32b;  mem[13] = h32c && w32c;

    unsigned bal[NREG];
#pragma unroll
    for (int r = 0; r < NREG; r++)
        bal[r] = __ballot_sync(0xffffffffu, tt && mem[r]);
    const int lane = tid & 31;
    if (lane < NREG) atomicAdd(&g_cnt[lane], __popc(bal[lane]));  // int atomics: deterministic
}

// ================= kernel C: norms + final combine =================
__global__ __launch_bounds__(1024) void kC(float* __restrict__ out) {
    const int b = blockIdx.x;
    const int c = threadIdx.x;
    const int warp = c >> 5;
    const int lane = c & 31;

    float val[NREG], ss[NREG];
#pragma unroll
    for (int r = 0; r < NREG; r++) {
        val[r] = g_vt[(r * B + b) * C + c];
        ss[r]  = val[r] * val[r];
    }
#pragma unroll
    for (int r = 0; r < NREG; r++)
        for (int o = 16; o > 0; o >>= 1)
            ss[r] += __shfl_xor_sync(0xffffffffu, ss[r], o);

    __shared__ float wsum[NREG][32];
    if (lane == 0) {
#pragma unroll
        for (int r = 0; r < NREG; r++) wsum[r][warp] = ss[r];
    }
    __syncthreads();

    __shared__ float scale_sh[NREG];
    if (warp < NREG) {
        float v = wsum[warp][lane];
        for (int o = 16; o > 0; o >>= 1)
            v += __shfl_xor_sync(0xffffffffu, v, o);
        if (lane == 0) {
            const float nrm = sqrtf(v);
            float wgt = (float)g_cnt[warp] / c_area[warp];
            if (wgt <= (1.0f / 3.0f)) wgt = 0.f;
            if (warp == 0) wgt *= 2.0f;           // full region appears twice
            scale_sh[warp] = wgt / (nrm + 1e-6f);
        }
    }
    __syncthreads();

    float o = 0.f;
#pragma unroll
    for (int r = 0; r < NREG; r++) o += val[r] * scale_sh[r];
    out[b * C + c] = o;
}

// ================= launch =================
extern "C" void kernel_launch(void* const* d_in, const int* in_sizes, int n_in,
                              void* d_out, int out_size) {
    const float* x = (const float*)d_in[0];
    float* out = (float*)d_out;
    kA<<<dim3(NGRP, B), 64>>>(x);
    kB1<<<64, 1024>>>();
    kB2<<<64, 1024>>>();
    kC<<<B, 1024>>>(out);
}